// round 1
// baseline (speedup 1.0000x reference)
#include <cuda_runtime.h>
#include <math.h>

#define N_ROWS 4096
#define DIM    1024
#define NCT    32     // 4096 / 128 column tiles

// Scratch (allocation-free rule: __device__ globals)
__device__ float g_anc[N_ROWS * DIM];      // normalized anchors, 16 MB
__device__ float g_pmax[N_ROWS * NCT];     // per (row, col-tile) max
__device__ int   g_pidx[N_ROWS * NCT];     // per (row, col-tile) argmax (global col)
__device__ int   g_count;

// ---------------------------------------------------------------------------
// K0: anc_hat[j] = x[j,1,:] / ||x[j,1,:]||  (one block per row, 256 threads)
// Also zeroes the match counter (must happen every graph replay).
// ---------------------------------------------------------------------------
__global__ void norm_kernel(const float* __restrict__ x) {
    const int j = blockIdx.x;
    const float* a = x + (size_t)j * 2048 + 1024;   // x[j,1,:]
    float4 v = reinterpret_cast<const float4*>(a)[threadIdx.x];
    float ss = v.x * v.x + v.y * v.y + v.z * v.z + v.w * v.w;

    __shared__ float wsum[8];
    __shared__ float s_rinv;
    #pragma unroll
    for (int o = 16; o > 0; o >>= 1) ss += __shfl_xor_sync(0xffffffffu, ss, o);
    if ((threadIdx.x & 31) == 0) wsum[threadIdx.x >> 5] = ss;
    __syncthreads();
    if (threadIdx.x == 0) {
        float t = 0.f;
        #pragma unroll
        for (int w = 0; w < 8; w++) t += wsum[w];
        s_rinv = 1.0f / sqrtf(fmaxf(t, 1e-30f));
        if (j == 0) g_count = 0;
    }
    __syncthreads();
    const float rinv = s_rinv;
    float4 o;
    o.x = v.x * rinv; o.y = v.y * rinv; o.z = v.z * rinv; o.w = v.w * rinv;
    reinterpret_cast<float4*>(g_anc + (size_t)j * DIM)[threadIdx.x] = o;
}

// ---------------------------------------------------------------------------
// K1: 128x128 tile NT SGEMM (A = pos rows of x, B = g_anc), double-buffered
// BK=8, 256 threads, 8x8 micro-tile per thread. Fused argmax over the
// block's 128 columns -> per-row partial (max, argmax).
// ---------------------------------------------------------------------------
__global__ __launch_bounds__(256, 2)
void gemm_argmax_kernel(const float* __restrict__ x) {
    __shared__ float As[2][8][128];
    __shared__ float Bs[2][8][128];
    __shared__ float redV[128][17];
    __shared__ int   redI[128][17];

    const int tid = threadIdx.x;
    const int bx  = blockIdx.x;       // column tile
    const int by  = blockIdx.y;       // row tile
    const int i0  = by * 128;
    const int j0  = bx * 128;

    // cooperative loads: thread -> (row within tile, 4-wide k chunk)
    const int lrow = tid >> 1;
    const int lk   = (tid & 1) << 2;

    const float* Ap = x      + (size_t)(i0 + lrow) * 2048 + lk;  // pos: stride 2048
    const float* Bp = g_anc + (size_t)(j0 + lrow) * 1024 + lk;

    const int tx = tid & 15;   // 16 column groups of 8
    const int ty = tid >> 4;   // 16 row groups of 8

    float acc[8][8];
    #pragma unroll
    for (int m = 0; m < 8; m++)
        #pragma unroll
        for (int n = 0; n < 8; n++) acc[m][n] = 0.f;

    // preload tile 0
    float4 a4 = *reinterpret_cast<const float4*>(Ap);
    float4 b4 = *reinterpret_cast<const float4*>(Bp);
    As[0][lk + 0][lrow] = a4.x; As[0][lk + 1][lrow] = a4.y;
    As[0][lk + 2][lrow] = a4.z; As[0][lk + 3][lrow] = a4.w;
    Bs[0][lk + 0][lrow] = b4.x; Bs[0][lk + 1][lrow] = b4.y;
    Bs[0][lk + 2][lrow] = b4.z; Bs[0][lk + 3][lrow] = b4.w;
    __syncthreads();

    int buf = 0;
    for (int k0 = 0; k0 < DIM; k0 += 8) {
        const bool more = (k0 + 8) < DIM;
        if (more) {
            a4 = *reinterpret_cast<const float4*>(Ap + k0 + 8);
            b4 = *reinterpret_cast<const float4*>(Bp + k0 + 8);
        }
        #pragma unroll
        for (int k = 0; k < 8; k++) {
            float ar[8], br[8];
            *reinterpret_cast<float4*>(ar)     = *reinterpret_cast<const float4*>(&As[buf][k][ty * 8]);
            *reinterpret_cast<float4*>(ar + 4) = *reinterpret_cast<const float4*>(&As[buf][k][ty * 8 + 4]);
            *reinterpret_cast<float4*>(br)     = *reinterpret_cast<const float4*>(&Bs[buf][k][tx * 8]);
            *reinterpret_cast<float4*>(br + 4) = *reinterpret_cast<const float4*>(&Bs[buf][k][tx * 8 + 4]);
            #pragma unroll
            for (int m = 0; m < 8; m++)
                #pragma unroll
                for (int n = 0; n < 8; n++)
                    acc[m][n] = fmaf(ar[m], br[n], acc[m][n]);
        }
        if (more) {
            const int nb = buf ^ 1;
            As[nb][lk + 0][lrow] = a4.x; As[nb][lk + 1][lrow] = a4.y;
            As[nb][lk + 2][lrow] = a4.z; As[nb][lk + 3][lrow] = a4.w;
            Bs[nb][lk + 0][lrow] = b4.x; Bs[nb][lk + 1][lrow] = b4.y;
            Bs[nb][lk + 2][lrow] = b4.z; Bs[nb][lk + 3][lrow] = b4.w;
            __syncthreads();
            buf = nb;
        }
    }

    // argmax epilogue: jnp.argmax takes the FIRST max -> strict '>' while
    // scanning columns in increasing order everywhere.
    #pragma unroll
    for (int m = 0; m < 8; m++) {
        float bv = acc[m][0]; int bi = 0;
        #pragma unroll
        for (int n = 1; n < 8; n++)
            if (acc[m][n] > bv) { bv = acc[m][n]; bi = n; }
        redV[ty * 8 + m][tx] = bv;
        redI[ty * 8 + m][tx] = tx * 8 + bi;
    }
    __syncthreads();
    if (tid < 128) {
        float bv = redV[tid][0]; int bi = redI[tid][0];
        #pragma unroll
        for (int t = 1; t < 16; t++) {
            float v = redV[tid][t];
            if (v > bv) { bv = v; bi = redI[tid][t]; }
        }
        g_pmax[(size_t)(i0 + tid) * NCT + bx] = bv;
        g_pidx[(size_t)(i0 + tid) * NCT + bx] = j0 + bi;
    }
}

// ---------------------------------------------------------------------------
// K2: reduce 32 column-tile partials per row; count argmax == row.
// ---------------------------------------------------------------------------
__global__ void reduce_kernel() {
    const int row = blockIdx.x * blockDim.x + threadIdx.x;
    if (row >= N_ROWS) return;
    const float* pv = g_pmax + (size_t)row * NCT;
    const int*   pi = g_pidx + (size_t)row * NCT;
    float bv = pv[0]; int bi = pi[0];
    #pragma unroll
    for (int c = 1; c < NCT; c++) {
        const float v = pv[c];
        if (v > bv) { bv = v; bi = pi[c]; }
    }
    if (bi == row) atomicAdd(&g_count, 1);
}

// ---------------------------------------------------------------------------
// K3: outputs. nloss is identically 1.0 (exp(t - stop_grad(t)) == exp(0)).
// ---------------------------------------------------------------------------
__global__ void final_kernel(float* __restrict__ out) {
    out[0] = 1.0f;
    out[1] = ((float)g_count / 4096.0f) * 100.0f;
}

extern "C" void kernel_launch(void* const* d_in, const int* in_sizes, int n_in,
                              void* d_out, int out_size) {
    const float* x = (const float*)d_in[0];
    float* out = (float*)d_out;

    norm_kernel<<<N_ROWS, 256>>>(x);
    dim3 grid(NCT, N_ROWS / 128);
    gemm_argmax_kernel<<<grid, 256>>>(x);
    reduce_kernel<<<N_ROWS / 256, 256>>>();
    final_kernel<<<1, 1>>>(out);
}

// round 3
// speedup vs baseline: 2.0382x; 2.0382x over previous
#include <cuda_runtime.h>
#include <cuda_bf16.h>
#include <cstdint>
#include <math.h>

#define N_ROWS 4096
#define DIM    1024
#define TMB    128                // CTA tile M
#define TNB    128                // CTA tile N
#define KSTEP  32                 // K per mainloop iteration
#define NITER  (DIM / KSTEP)      // 32
#define NCT    (N_ROWS / TNB)     // 32 column tiles

// SMEM stage: A block 128 rows x 128B (hi 64B | lo 64B), B block same.
#define STAGE_A     0
#define STAGE_B     16384
#define STAGE_BYTES 32768
#define SMEM_BYTES  (2 * STAGE_BYTES + 1024)

// ---------------- device scratch (allocation-free rule) ----------------
__device__ __nv_bfloat16 g_Ah[N_ROWS * DIM];
__device__ __nv_bfloat16 g_Al[N_ROWS * DIM];
__device__ __nv_bfloat16 g_Bh[N_ROWS * DIM];
__device__ __nv_bfloat16 g_Bl[N_ROWS * DIM];
__device__ float g_pmax[N_ROWS * NCT];
__device__ int   g_pidx[N_ROWS * NCT];
__device__ int   g_count;

// ---------------- helpers ----------------
__device__ __forceinline__ uint32_t smem_u32(const void* p) {
    uint32_t a;
    asm("{ .reg .u64 t; cvta.to.shared.u64 t, %1; cvt.u32.u64 %0, t; }" : "=r"(a) : "l"(p));
    return a;
}
#define SWZ(bo) ((bo) ^ (((bo) >> 3) & 0x70))

__device__ __forceinline__ void cp_async16(uint32_t dst, const void* src) {
    asm volatile("cp.async.cg.shared.global [%0], [%1], 16;" :: "r"(dst), "l"(src));
}
__device__ __forceinline__ void cp_commit() {
    asm volatile("cp.async.commit_group;" ::: "memory");
}
template <int N>
__device__ __forceinline__ void cp_wait() {
    asm volatile("cp.async.wait_group %0;" :: "n"(N) : "memory");
}

__device__ __forceinline__ void ldsm_x4(uint32_t addr, uint32_t& r0, uint32_t& r1,
                                        uint32_t& r2, uint32_t& r3) {
    asm volatile("ldmatrix.sync.aligned.m8n8.x4.shared.b16 {%0,%1,%2,%3}, [%4];"
                 : "=r"(r0), "=r"(r1), "=r"(r2), "=r"(r3) : "r"(addr));
}

__device__ __forceinline__ void mma_bf16(float* d, const uint32_t* a, const uint32_t* b) {
    asm volatile(
        "mma.sync.aligned.m16n8k16.row.col.f32.bf16.bf16.f32 "
        "{%0,%1,%2,%3}, {%4,%5,%6,%7}, {%8,%9}, {%0,%1,%2,%3};"
        : "+f"(d[0]), "+f"(d[1]), "+f"(d[2]), "+f"(d[3])
        : "r"(a[0]), "r"(a[1]), "r"(a[2]), "r"(a[3]), "r"(b[0]), "r"(b[1]));
}

// ---------------------------------------------------------------------------
// K0: bf16 hi/lo splits. A = x[:,0,:] (pos), B = x[:,1,:]/||x[:,1,:]||.
// ---------------------------------------------------------------------------
__device__ __forceinline__ uint32_t pk2(float a, float b) {
    __nv_bfloat162 t = __floats2bfloat162_rn(a, b);
    return *reinterpret_cast<uint32_t*>(&t);
}

__global__ void prep_kernel(const float* __restrict__ x) {
    const int j = blockIdx.x;
    const int t = threadIdx.x;
    const float4 p = reinterpret_cast<const float4*>(x + (size_t)j * 2048)[t];
    const float4 a = reinterpret_cast<const float4*>(x + (size_t)j * 2048 + 1024)[t];

    float ss = a.x * a.x + a.y * a.y + a.z * a.z + a.w * a.w;
    __shared__ float wsum[8];
    __shared__ float s_rinv;
    #pragma unroll
    for (int o = 16; o > 0; o >>= 1) ss += __shfl_xor_sync(0xffffffffu, ss, o);
    if ((t & 31) == 0) wsum[t >> 5] = ss;
    __syncthreads();
    if (t == 0) {
        float tot = 0.f;
        #pragma unroll
        for (int w = 0; w < 8; w++) tot += wsum[w];
        s_rinv = 1.0f / sqrtf(fmaxf(tot, 1e-30f));
        if (j == 0) g_count = 0;
    }
    __syncthreads();
    const float rinv = s_rinv;

    float pv[4] = {p.x, p.y, p.z, p.w};
    float av[4] = {a.x * rinv, a.y * rinv, a.z * rinv, a.w * rinv};
    float ph[4], pl[4], ah[4], al[4];
    #pragma unroll
    for (int i = 0; i < 4; i++) {
        __nv_bfloat16 h = __float2bfloat16(pv[i]);
        ph[i] = __bfloat162float(h);
        pl[i] = pv[i] - ph[i];
        h = __float2bfloat16(av[i]);
        ah[i] = __bfloat162float(h);
        al[i] = av[i] - ah[i];
    }
    const size_t o = (size_t)j * DIM;
    uint2 v;
    v.x = pk2(ph[0], ph[1]); v.y = pk2(ph[2], ph[3]);
    reinterpret_cast<uint2*>(g_Ah + o)[t] = v;
    v.x = pk2(pl[0], pl[1]); v.y = pk2(pl[2], pl[3]);
    reinterpret_cast<uint2*>(g_Al + o)[t] = v;
    v.x = pk2(ah[0], ah[1]); v.y = pk2(ah[2], ah[3]);
    reinterpret_cast<uint2*>(g_Bh + o)[t] = v;
    v.x = pk2(al[0], al[1]); v.y = pk2(al[2], al[3]);
    reinterpret_cast<uint2*>(g_Bl + o)[t] = v;
}

// ---------------------------------------------------------------------------
// K1: compensated bf16 GEMM via mma.sync (HMMA), 128x128 tile, cp.async
// double buffer, fused argmax epilogue.
// ---------------------------------------------------------------------------
__global__ __launch_bounds__(256) void gemm_kernel() {
    extern __shared__ char dyn_smem[];
    char* sm = (char*)((((uintptr_t)dyn_smem) + 1023) & ~(uintptr_t)1023);
    const uint32_t sbase = smem_u32(sm);

    const int tid = threadIdx.x;
    const int wid = tid >> 5;
    const int lid = tid & 31;
    const int i0 = blockIdx.y * TMB;
    const int j0 = blockIdx.x * TNB;

    // warp layout: 2 (m) x 4 (n); warp tile 64x32
    const int wm = (wid >> 2) * 64;
    const int wn = (wid & 3) * 32;

    // ---- load mapping: thread -> (row, hi/lo half), 4x 16B chunks each ----
    const int lrow = tid >> 1;        // 0..127
    const int lsel = tid & 1;         // 0 = hi, 1 = lo
    const __nv_bfloat16* gA = (lsel ? g_Al : g_Ah) + (size_t)(i0 + lrow) * DIM;
    const __nv_bfloat16* gB = (lsel ? g_Bl : g_Bh) + (size_t)(j0 + lrow) * DIM;

    float acc[4][4][4];
    #pragma unroll
    for (int m = 0; m < 4; m++)
        #pragma unroll
        for (int n = 0; n < 4; n++)
            #pragma unroll
            for (int e = 0; e < 4; e++) acc[m][n][e] = 0.f;

    // ldmatrix lane addressing
    const int a_row = lid & 15;            // rows 0..15 within frag
    const int a_u   = lid >> 4;            // 16B unit (k sub-chunk)
    const int b_row = (lid & 7) + ((lid >> 4) << 3);   // n row within 16
    const int b_u   = (lid >> 3) & 1;

    auto load_stage = [&](int c, int buf) {
        const uint32_t st = sbase + buf * STAGE_BYTES;
        const __nv_bfloat16* ga = gA + c * KSTEP;
        const __nv_bfloat16* gb = gB + c * KSTEP;
        #pragma unroll
        for (int q = 0; q < 4; q++) {
            const uint32_t so = SWZ((uint32_t)(lrow * 128 + lsel * 64 + q * 16));
            cp_async16(st + STAGE_A + so, ga + q * 8);
            cp_async16(st + STAGE_B + so, gb + q * 8);
        }
        cp_commit();
    };

    auto compute_stage = [&](int buf) {
        const uint32_t stA = sbase + buf * STAGE_BYTES + STAGE_A;
        const uint32_t stB = sbase + buf * STAGE_BYTES + STAGE_B;
        #pragma unroll
        for (int kk = 0; kk < 2; kk++) {
            uint32_t ah[4][4], al[4][4], bh[4][2], bl[4][2];
            #pragma unroll
            for (int mf = 0; mf < 4; mf++) {
                const uint32_t bo = (uint32_t)((wm + mf * 16 + a_row) * 128 + kk * 32 + a_u * 16);
                ldsm_x4(stA + SWZ(bo),      ah[mf][0], ah[mf][1], ah[mf][2], ah[mf][3]);
                ldsm_x4(stA + SWZ(bo + 64), al[mf][0], al[mf][1], al[mf][2], al[mf][3]);
            }
            #pragma unroll
            for (int nf2 = 0; nf2 < 2; nf2++) {
                const uint32_t bo = (uint32_t)((wn + nf2 * 16 + b_row) * 128 + kk * 32 + b_u * 16);
                uint32_t r0, r1, r2, r3;
                ldsm_x4(stB + SWZ(bo), r0, r1, r2, r3);
                bh[nf2 * 2][0] = r0; bh[nf2 * 2][1] = r1;
                bh[nf2 * 2 + 1][0] = r2; bh[nf2 * 2 + 1][1] = r3;
                ldsm_x4(stB + SWZ(bo + 64), r0, r1, r2, r3);
                bl[nf2 * 2][0] = r0; bl[nf2 * 2][1] = r1;
                bl[nf2 * 2 + 1][0] = r2; bl[nf2 * 2 + 1][1] = r3;
            }
            #pragma unroll
            for (int mf = 0; mf < 4; mf++)
                #pragma unroll
                for (int nf = 0; nf < 4; nf++)
                    mma_bf16(acc[mf][nf], ah[mf], bh[nf]);
            #pragma unroll
            for (int mf = 0; mf < 4; mf++)
                #pragma unroll
                for (int nf = 0; nf < 4; nf++)
                    mma_bf16(acc[mf][nf], ah[mf], bl[nf]);
            #pragma unroll
            for (int mf = 0; mf < 4; mf++)
                #pragma unroll
                for (int nf = 0; nf < 4; nf++)
                    mma_bf16(acc[mf][nf], al[mf], bh[nf]);
        }
    };

    // ---- pipeline: 2 stages ----
    load_stage(0, 0);
    load_stage(1, 1);

    int buf = 0;
    #pragma unroll 1
    for (int c = 0; c < NITER; ++c) {
        if (c < NITER - 1) cp_wait<1>(); else cp_wait<0>();
        __syncthreads();
        compute_stage(buf);
        __syncthreads();
        if (c + 2 < NITER) load_stage(c + 2, buf);
        buf ^= 1;
    }

    // ---- argmax epilogue (first-max semantics: ascending cols, strict >,
    //      ties across lanes/warps resolved to lower column index) ----
    const int quad = lid & 3;
    float* redV = (float*)sm;                    // [128][4]
    int*   redI = (int*)(sm + 128 * 4 * 4);      // [128][4]

    #pragma unroll
    for (int mf = 0; mf < 4; mf++) {
        #pragma unroll
        for (int half = 0; half < 2; half++) {   // d0/d1 row, d2/d3 row
            float bv = -INFINITY;
            int bi = 0;
            #pragma unroll
            for (int nf = 0; nf < 4; nf++) {
                #pragma unroll
                for (int i = 0; i < 2; i++) {
                    const float v = acc[mf][nf][half * 2 + i];
                    const int col = nf * 8 + quad * 2 + i;
                    if (v > bv) { bv = v; bi = col; }
                }
            }
            #pragma unroll
            for (int o = 1; o <= 2; o <<= 1) {
                const float vo = __shfl_xor_sync(0xffffffffu, bv, o);
                const int io = __shfl_xor_sync(0xffffffffu, bi, o);
                if (vo > bv || (vo == bv && io < bi)) { bv = vo; bi = io; }
            }
            if (quad == 0) {
                const int row = wm + mf * 16 + (lid >> 2) + half * 8;   // 0..127
                redV[row * 4 + (wid & 3)] = bv;
                redI[row * 4 + (wid & 3)] = wn + bi;
            }
        }
    }
    __syncthreads();
    if (tid < 128) {
        float bv = redV[tid * 4]; int bi = redI[tid * 4];
        #pragma unroll
        for (int w = 1; w < 4; w++) {
            const float v = redV[tid * 4 + w];
            if (v > bv) { bv = v; bi = redI[tid * 4 + w]; }
        }
        g_pmax[(size_t)(i0 + tid) * NCT + blockIdx.x] = bv;
        g_pidx[(size_t)(i0 + tid) * NCT + blockIdx.x] = j0 + bi;
    }
}

// ---------------------------------------------------------------------------
// K2: reduce 32 column-tile partials per row; count argmax == row.
// ---------------------------------------------------------------------------
__global__ void reduce_kernel() {
    const int row = blockIdx.x * blockDim.x + threadIdx.x;
    if (row >= N_ROWS) return;
    const float* pv = g_pmax + (size_t)row * NCT;
    const int*   pi = g_pidx + (size_t)row * NCT;
    float bv = pv[0]; int bi = pi[0];
    #pragma unroll
    for (int c = 1; c < NCT; c++) {
        const float v = pv[c];
        if (v > bv) { bv = v; bi = pi[c]; }
    }
    if (bi == row) atomicAdd(&g_count, 1);
}

// ---------------------------------------------------------------------------
// K3: outputs. nloss == 1.0 exactly (exp(t - stop_grad(t)) == exp(0)).
// ---------------------------------------------------------------------------
__global__ void final_kernel(float* __restrict__ out) {
    out[0] = 1.0f;
    out[1] = ((float)g_count / 4096.0f) * 100.0f;
}

extern "C" void kernel_launch(void* const* d_in, const int* in_sizes, int n_in,
                              void* d_out, int out_size) {
    const float* x = (const float*)d_in[0];
    float* out = (float*)d_out;

    cudaFuncSetAttribute(gemm_kernel, cudaFuncAttributeMaxDynamicSharedMemorySize, SMEM_BYTES);

    prep_kernel<<<N_ROWS, 256>>>(x);
    dim3 grid(N_ROWS / TNB, N_ROWS / TMB);   // (32, 32)
    gemm_kernel<<<grid, 256, SMEM_BYTES>>>();
    reduce_kernel<<<N_ROWS / 256, 256>>>();
    final_kernel<<<1, 1>>>(out);
}

// round 4
// speedup vs baseline: 4.6528x; 2.2828x over previous
#include <cuda_runtime.h>
#include <cuda_bf16.h>
#include <cstdint>
#include <math.h>

#define N_ROWS 4096
#define DIM    1024
#define TMB    128
#define TNB    128
#define KSTEP  64                 // bf16 per mainloop iter = 128B row
#define NITER  (DIM / KSTEP)      // 16
#define NCT    (N_ROWS / TNB)     // 32 column tiles
#define THR    0.03f

#define STAGE_A     0
#define STAGE_B     16384
#define STAGE_BYTES 32768
#define SMEM_BYTES  (2 * STAGE_BYTES + 1024)

// ---------------- device scratch ----------------
__device__ __nv_bfloat16 g_Ah[N_ROWS * DIM];   // bf16(pos)
__device__ __nv_bfloat16 g_Bh[N_ROWS * DIM];   // bf16(anchor_hat)
__device__ float         g_Bf[N_ROWS * DIM];   // fp32 anchor_hat (for rescore)
__device__ float g_v1[N_ROWS * NCT];
__device__ int   g_i1[N_ROWS * NCT];
__device__ float g_v2[N_ROWS * NCT];
__device__ int   g_i2[N_ROWS * NCT];
__device__ int   g_flag[N_ROWS];
__device__ int   g_count;

// ---------------- helpers ----------------
__device__ __forceinline__ uint32_t smem_u32(const void* p) {
    uint32_t a;
    asm("{ .reg .u64 t; cvta.to.shared.u64 t, %1; cvt.u32.u64 %0, t; }" : "=r"(a) : "l"(p));
    return a;
}
#define SWZ(bo) ((bo) ^ (((bo) >> 3) & 0x70))

__device__ __forceinline__ void cp_async16(uint32_t dst, const void* src) {
    asm volatile("cp.async.cg.shared.global [%0], [%1], 16;" :: "r"(dst), "l"(src));
}
__device__ __forceinline__ void cp_commit() {
    asm volatile("cp.async.commit_group;" ::: "memory");
}
template <int N>
__device__ __forceinline__ void cp_wait() {
    asm volatile("cp.async.wait_group %0;" :: "n"(N) : "memory");
}
__device__ __forceinline__ void ldsm_x4(uint32_t addr, uint32_t& r0, uint32_t& r1,
                                        uint32_t& r2, uint32_t& r3) {
    asm volatile("ldmatrix.sync.aligned.m8n8.x4.shared.b16 {%0,%1,%2,%3}, [%4];"
                 : "=r"(r0), "=r"(r1), "=r"(r2), "=r"(r3) : "r"(addr));
}
__device__ __forceinline__ void mma_bf16(float* d, const uint32_t* a, const uint32_t* b) {
    asm volatile(
        "mma.sync.aligned.m16n8k16.row.col.f32.bf16.bf16.f32 "
        "{%0,%1,%2,%3}, {%4,%5,%6,%7}, {%8,%9}, {%0,%1,%2,%3};"
        : "+f"(d[0]), "+f"(d[1]), "+f"(d[2]), "+f"(d[3])
        : "r"(a[0]), "r"(a[1]), "r"(a[2]), "r"(a[3]), "r"(b[0]), "r"(b[1]));
}
__device__ __forceinline__ uint32_t pk2(float a, float b) {
    __nv_bfloat162 t = __floats2bfloat162_rn(a, b);
    return *reinterpret_cast<uint32_t*>(&t);
}

// ---------------------------------------------------------------------------
// K0: bf16 casts + fp32 normalized anchors. Zeroes match counter.
// ---------------------------------------------------------------------------
__global__ void prep_kernel(const float* __restrict__ x) {
    const int j = blockIdx.x;
    const int t = threadIdx.x;
    const float4 p = reinterpret_cast<const float4*>(x + (size_t)j * 2048)[t];
    const float4 a = reinterpret_cast<const float4*>(x + (size_t)j * 2048 + 1024)[t];

    float ss = a.x * a.x + a.y * a.y + a.z * a.z + a.w * a.w;
    __shared__ float wsum[8];
    __shared__ float s_rinv;
    #pragma unroll
    for (int o = 16; o > 0; o >>= 1) ss += __shfl_xor_sync(0xffffffffu, ss, o);
    if ((t & 31) == 0) wsum[t >> 5] = ss;
    __syncthreads();
    if (t == 0) {
        float tot = 0.f;
        #pragma unroll
        for (int w = 0; w < 8; w++) tot += wsum[w];
        s_rinv = 1.0f / sqrtf(fmaxf(tot, 1e-30f));
        if (j == 0) g_count = 0;
    }
    __syncthreads();
    const float rinv = s_rinv;

    float4 an;
    an.x = a.x * rinv; an.y = a.y * rinv; an.z = a.z * rinv; an.w = a.w * rinv;
    const size_t o = (size_t)j * DIM;
    reinterpret_cast<float4*>(g_Bf + o)[t] = an;
    uint2 v;
    v.x = pk2(p.x, p.y);   v.y = pk2(p.z, p.w);
    reinterpret_cast<uint2*>(g_Ah + o)[t] = v;
    v.x = pk2(an.x, an.y); v.y = pk2(an.z, an.w);
    reinterpret_cast<uint2*>(g_Bh + o)[t] = v;
}

// ---------------------------------------------------------------------------
// K1: bf16 hi-only GEMM via mma.sync, 128x128 tile, cp.async double buffer,
// fused per-tile top-2 epilogue.
// ---------------------------------------------------------------------------
__global__ __launch_bounds__(256) void gemm_kernel() {
    extern __shared__ char dyn_smem[];
    char* sm = (char*)((((uintptr_t)dyn_smem) + 1023) & ~(uintptr_t)1023);
    const uint32_t sbase = smem_u32(sm);

    const int tid = threadIdx.x;
    const int wid = tid >> 5;
    const int lid = tid & 31;
    const int i0 = blockIdx.y * TMB;
    const int j0 = blockIdx.x * TNB;

    // 8 warps: 2 (m) x 4 (n); warp tile 64x32
    const int wm = (wid >> 2) * 64;
    const int wn = (wid & 3) * 32;

    // load mapping: 2 threads per 128B row (each 64B half)
    const int lrow = tid >> 1;
    const int lhalf = tid & 1;
    const __nv_bfloat16* gA = g_Ah + (size_t)(i0 + lrow) * DIM + lhalf * 32;
    const __nv_bfloat16* gB = g_Bh + (size_t)(j0 + lrow) * DIM + lhalf * 32;

    float acc[4][4][4];
    #pragma unroll
    for (int m = 0; m < 4; m++)
        #pragma unroll
        for (int n = 0; n < 4; n++)
            #pragma unroll
            for (int e = 0; e < 4; e++) acc[m][n][e] = 0.f;

    const int a_row = lid & 15;
    const int a_u   = lid >> 4;
    const int b_row = (lid & 7) + ((lid >> 4) << 3);
    const int b_u   = (lid >> 3) & 1;

    auto load_stage = [&](int c, int buf) {
        const uint32_t st = sbase + buf * STAGE_BYTES;
        const __nv_bfloat16* ga = gA + c * KSTEP;
        const __nv_bfloat16* gb = gB + c * KSTEP;
        #pragma unroll
        for (int q = 0; q < 4; q++) {
            const uint32_t so = SWZ((uint32_t)(lrow * 128 + lhalf * 64 + q * 16));
            cp_async16(st + STAGE_A + so, ga + q * 8);
            cp_async16(st + STAGE_B + so, gb + q * 8);
        }
        cp_commit();
    };

    auto compute_stage = [&](int buf) {
        const uint32_t stA = sbase + buf * STAGE_BYTES + STAGE_A;
        const uint32_t stB = sbase + buf * STAGE_BYTES + STAGE_B;
        #pragma unroll
        for (int kk = 0; kk < 4; kk++) {
            uint32_t ah[4][4], bh[4][2];
            #pragma unroll
            for (int mf = 0; mf < 4; mf++) {
                const uint32_t bo = (uint32_t)((wm + mf * 16 + a_row) * 128 + kk * 32 + a_u * 16);
                ldsm_x4(stA + SWZ(bo), ah[mf][0], ah[mf][1], ah[mf][2], ah[mf][3]);
            }
            #pragma unroll
            for (int nf2 = 0; nf2 < 2; nf2++) {
                const uint32_t bo = (uint32_t)((wn + nf2 * 16 + b_row) * 128 + kk * 32 + b_u * 16);
                uint32_t r0, r1, r2, r3;
                ldsm_x4(stB + SWZ(bo), r0, r1, r2, r3);
                bh[nf2 * 2][0] = r0;     bh[nf2 * 2][1] = r1;
                bh[nf2 * 2 + 1][0] = r2; bh[nf2 * 2 + 1][1] = r3;
            }
            #pragma unroll
            for (int mf = 0; mf < 4; mf++)
                #pragma unroll
                for (int nf = 0; nf < 4; nf++)
                    mma_bf16(acc[mf][nf], ah[mf], bh[nf]);
        }
    };

    load_stage(0, 0);
    load_stage(1, 1);
    int buf = 0;
    #pragma unroll 1
    for (int c = 0; c < NITER; ++c) {
        if (c < NITER - 1) cp_wait<1>(); else cp_wait<0>();
        __syncthreads();
        compute_stage(buf);
        __syncthreads();
        if (c + 2 < NITER) load_stage(c + 2, buf);
        buf ^= 1;
    }

    // ---- top-2 epilogue (first-max semantics preserved by ascending-col
    //      scan with strict > and lower-index-wins tie-breaks) ----
    const int quad = lid & 3;
    float* rV1 = (float*)sm;                  // [128][4]
    int*   rI1 = (int*)(sm + 2048);
    float* rV2 = (float*)(sm + 4096);
    int*   rI2 = (int*)(sm + 6144);

    #pragma unroll
    for (int mf = 0; mf < 4; mf++) {
        #pragma unroll
        for (int half = 0; half < 2; half++) {
            float v1 = -INFINITY, v2 = -INFINITY;
            int i1 = 0, i2 = 0;
            #pragma unroll
            for (int nf = 0; nf < 4; nf++) {
                #pragma unroll
                for (int i = 0; i < 2; i++) {
                    const float v = acc[mf][nf][half * 2 + i];
                    const int c = nf * 8 + quad * 2 + i;
                    if (v > v1) { v2 = v1; i2 = i1; v1 = v; i1 = c; }
                    else if (v > v2) { v2 = v; i2 = c; }
                }
            }
            #pragma unroll
            for (int o = 1; o <= 2; o <<= 1) {
                const float ov1 = __shfl_xor_sync(0xffffffffu, v1, o);
                const int   oi1 = __shfl_xor_sync(0xffffffffu, i1, o);
                const float ov2 = __shfl_xor_sync(0xffffffffu, v2, o);
                const int   oi2 = __shfl_xor_sync(0xffffffffu, i2, o);
                if (ov1 > v1 || (ov1 == v1 && oi1 < i1)) {
                    if (v1 > ov2 || (v1 == ov2 && i1 < oi2)) { v2 = v1; i2 = i1; }
                    else { v2 = ov2; i2 = oi2; }
                    v1 = ov1; i1 = oi1;
                } else {
                    if (ov1 > v2) { v2 = ov1; i2 = oi1; }
                }
            }
            if (quad == 0) {
                const int row = wm + mf * 16 + (lid >> 2) + half * 8;
                const int w = wid & 3;
                rV1[row * 4 + w] = v1; rI1[row * 4 + w] = wn + i1;
                rV2[row * 4 + w] = v2; rI2[row * 4 + w] = wn + i2;
            }
        }
    }
    __syncthreads();
    if (tid < 128) {
        float V1 = rV1[tid * 4], V2 = rV2[tid * 4];
        int I1 = rI1[tid * 4], I2 = rI2[tid * 4];
        #pragma unroll
        for (int w = 1; w < 4; w++) {
            const float v1 = rV1[tid * 4 + w], v2 = rV2[tid * 4 + w];
            const int i1 = rI1[tid * 4 + w], i2 = rI2[tid * 4 + w];
            if (v1 > V1) {
                if (V1 >= v2) { V2 = V1; I2 = I1; } else { V2 = v2; I2 = i2; }
                V1 = v1; I1 = i1;
            } else if (v1 > V2) { V2 = v1; I2 = i1; }
        }
        const size_t o = (size_t)(i0 + tid) * NCT + blockIdx.x;
        g_v1[o] = V1; g_i1[o] = j0 + I1;
        g_v2[o] = V2; g_i2[o] = j0 + I2;
    }
}

// ---------------------------------------------------------------------------
// K2: merge 32 tile top-2s per row. Certain rows counted; ambiguous flagged.
// ---------------------------------------------------------------------------
__global__ void reduce_kernel() {
    const int row = blockIdx.x * blockDim.x + threadIdx.x;
    if (row >= N_ROWS) return;
    const size_t o = (size_t)row * NCT;
    float V1 = g_v1[o], V2 = g_v2[o];
    int I1 = g_i1[o];
    #pragma unroll
    for (int t = 1; t < NCT; t++) {
        const float v1 = g_v1[o + t], v2 = g_v2[o + t];
        // tiles scanned ascending: strict > keeps first-max
        if (v1 > V1) {
            V2 = fmaxf(V1, v2);
            V1 = v1; I1 = g_i1[o + t];
        } else {
            V2 = fmaxf(V2, v1);
        }
    }
    const bool amb = (V1 - V2) < THR;
    g_flag[row] = amb ? 1 : 0;
    if (!amb && I1 == row) atomicAdd(&g_count, 1);
}

// ---------------------------------------------------------------------------
// K3: exact fp32 rescore of flagged rows over the 64 per-tile top-2 columns.
// ---------------------------------------------------------------------------
__global__ __launch_bounds__(128) void rescore_kernel(const float* __restrict__ x) {
    const int row = blockIdx.x;
    if (!g_flag[row]) return;

    __shared__ float sv[64];
    __shared__ int si[64];
    const int tid = threadIdx.x;
    const int wid = tid >> 5;
    const int lid = tid & 31;
    const float* a = x + (size_t)row * 2048;   // pos row, fp32

    for (int s = 0; s < 16; s++) {
        const int slot = wid * 16 + s;
        const int tile = slot >> 1;
        const size_t o = (size_t)row * NCT + tile;
        const int cand = (slot & 1) ? g_i2[o] : g_i1[o];
        const float* b = g_Bf + (size_t)cand * DIM;
        float sum = 0.f;
        #pragma unroll 8
        for (int k = lid; k < DIM; k += 32) sum = fmaf(a[k], b[k], sum);
        #pragma unroll
        for (int of = 16; of > 0; of >>= 1) sum += __shfl_xor_sync(0xffffffffu, sum, of);
        if (lid == 0) { sv[slot] = sum; si[slot] = cand; }
    }
    __syncthreads();
    if (tid == 0) {
        float best = -INFINITY;
        int bi = 1 << 30;
        for (int s = 0; s < 64; s++) {
            const float v = sv[s];
            if (v > best || (v == best && si[s] < bi)) { best = v; bi = si[s]; }
        }
        if (bi == row) atomicAdd(&g_count, 1);
    }
}

// ---------------------------------------------------------------------------
// K4: outputs. nloss == 1.0 exactly.
// ---------------------------------------------------------------------------
__global__ void final_kernel(float* __restrict__ out) {
    out[0] = 1.0f;
    out[1] = ((float)g_count / 4096.0f) * 100.0f;
}

extern "C" void kernel_launch(void* const* d_in, const int* in_sizes, int n_in,
                              void* d_out, int out_size) {
    const float* x = (const float*)d_in[0];
    float* out = (float*)d_out;

    cudaFuncSetAttribute(gemm_kernel, cudaFuncAttributeMaxDynamicSharedMemorySize, SMEM_BYTES);

    prep_kernel<<<N_ROWS, 256>>>(x);
    dim3 grid(N_ROWS / TNB, N_ROWS / TMB);   // (32, 32)
    gemm_kernel<<<grid, 256, SMEM_BYTES>>>();
    reduce_kernel<<<N_ROWS / 256, 256>>>();
    rescore_kernel<<<N_ROWS, 128>>>(x);
    final_kernel<<<1, 1>>>(out);
}